// round 9
// baseline (speedup 1.0000x reference)
#include <cuda_runtime.h>
#include <math.h>

// UserCollaborativeFiltering: one warp per TWO batch elements.
//   pred[b] = avg_u + sum_k w_k * (r_k - avg_k),  w_k = topsim_k / (sum topsim + 1e-8)
//
// R7 change vs R6: 2-query batching per warp. Both queries' gathers (10
// independent scattered LDGs + 20 L2-table loads) are issued before any top-k
// compute, doubling per-warp memory-level parallelism; query 0's compute
// overlaps query 1's in-flight loads. Traffic is tag-capacity-bound in L2
// (2.33M distinct lines > 1M tags), so the ~150MB/launch DRAM floor stands —
// this round is purely about keeping the HBM queue full.
//
// MAXW*32 must cover U (U=142 -> MAXW=5 supports U<=160).

#define FULLMASK 0xffffffffu
#define MAXW 5
#define NQ 2

// order-preserving float->u32 key; 0 is below every valid key (used for
// padding + knockout). Exactly invertible for the values we decode (key!=0).
__device__ __forceinline__ unsigned f2key(float f) {
    unsigned b = __float_as_uint(f);
    return (b & 0x80000000u) ? ~b : (b | 0x80000000u);
}
__device__ __forceinline__ float key2f(unsigned k) {
    unsigned b = (k & 0x80000000u) ? (k & 0x7fffffffu) : ~k;
    return __uint_as_float(b);
}

__global__ void __launch_bounds__(256, 5) ucf_kernel(
    const float* __restrict__ qos,    // (T,U,I)
    const float* __restrict__ uavg,   // (T,U)
    const float* __restrict__ usim,   // (U,U)
    const int*   __restrict__ uid,    // (B,)
    const int*   __restrict__ iid,    // (B,)
    const int*   __restrict__ tidv,   // (B,)
    const int*   __restrict__ topk_ptr,
    float*       __restrict__ out,    // (B,)
    int U, int I, int B)
{
    const int warp = (blockIdx.x * blockDim.x + threadIdx.x) >> 5;
    const int lane = threadIdx.x & 31;
    const int q0   = warp * NQ;
    if (q0 >= B) return;

    int kk = topk_ptr ? __ldg(topk_ptr) : 10;
    if (kk > U) kk = U;
    if (kk < 0) kk = 0;

    float rv[NQ][MAXW], sk[NQ][MAXW], av[NQ][MAXW];
    float avg_u[NQ];
    bool  valid[NQ];

    // ── Phase 1: issue ALL gathers for both queries before any compute.
    // 10 independent scattered qos loads in flight per warp (plus 20 cheap
    // L2-table loads). No dependence between queries -> ptxas hoists issues.
#pragma unroll
    for (int p = 0; p < NQ; p++) {
        const int q = q0 + p;
        valid[p] = (q < B);
        const int u  = valid[p] ? uid[q]  : 0;
        const int it = valid[p] ? iid[q]  : 0;
        const int tt = valid[p] ? tidv[q] : 0;

        const float* qcol = qos + (size_t)tt * U * I + it;   // + v*I
        const float* srow = usim + (size_t)u * U;
        const float* arow = uavg + (size_t)tt * U;
        avg_u[p] = __ldg(arow + u);

#pragma unroll
        for (int j = 0; j < MAXW; j++) {
            const int v = lane + 32 * j;
            rv[p][j] = 0.0f; sk[p][j] = 0.0f; av[p][j] = 0.0f;
            if (valid[p] && v < U) {
                rv[p][j] = __ldg(qcol + (size_t)v * I);  // scattered, stride I
                sk[p][j] = __ldg(srow + v);              // L2-resident 80KB
                av[p][j] = __ldg(arow + v);              // L2-resident 36KB
            }
        }
    }

    // ── Phase 2: top-k + weighted sum per query.
#pragma unroll
    for (int p = 0; p < NQ; p++) {
        if (!valid[p]) break;

        // keys in place of sims: rated -> ordered(sim), unrated ->
        // ordered(0.0) (participates in top_k!), out-of-range -> 0
        unsigned kv[MAXW];
#pragma unroll
        for (int j = 0; j < MAXW; j++) {
            const int v = lane + 32 * j;
            const float s = (rv[p][j] > 0.0f) ? sk[p][j] : 0.0f;
            kv[j] = (v < U) ? f2key(s) : 0u;
        }

        float ssum = 0.0f;   // distributed across lanes
        float acc  = 0.0f;

        for (int k = 0; k < kk; k++) {
            unsigned lk = kv[0];
#pragma unroll
            for (int j = 1; j < MAXW; j++) lk = max(lk, kv[j]);

            const unsigned wk = __reduce_max_sync(FULLMASK, lk);  // REDUX.MAX
            if (wk == 0u) break;   // exhausted (can't happen for U>=kk)

            // every lane holding the winning key accumulates + knocks out.
            // Dup keys only occur at the zero-sim key (weight 0), so this is
            // value-identical to single-leader selection.
#pragma unroll
            for (int j = 0; j < MAXW; j++) {
                if (kv[j] == wk) {
                    const float s = key2f(wk);
                    acc  = fmaf(s, rv[p][j] - av[p][j], acc);
                    ssum += s;
                    kv[j] = 0u;
                }
            }
        }

#pragma unroll
        for (int off = 16; off; off >>= 1) {
            acc  += __shfl_xor_sync(FULLMASK, acc,  off);
            ssum += __shfl_xor_sync(FULLMASK, ssum, off);
        }

        if (lane == 0) {
            const float denom = ssum + 1e-8f;
            float inv = 1.0f / denom;
            if (!isfinite(inv)) inv = 0.0f;   // mirrors nan_to_num on weights
            out[q0 + p] = avg_u[p] + acc * inv;
        }
    }
}

extern "C" void kernel_launch(void* const* d_in, const int* in_sizes, int n_in,
                              void* d_out, int out_size) {
    const float* qos  = (const float*)d_in[0];
    const float* uavg = (const float*)d_in[1];
    const float* usim = (const float*)d_in[2];
    const int*   uid  = (const int*)d_in[3];
    const int*   iid  = (const int*)d_in[4];
    const int*   tidv = (const int*)d_in[5];
    const int*   topk = (n_in >= 7) ? (const int*)d_in[6] : nullptr;

    // Derive dims: sizes are [T*U*I, T*U, U*U, B, B, B, 1]
    int U = (int)(sqrt((double)in_sizes[2]) + 0.5);
    int I = in_sizes[0] / in_sizes[1];   // (T*U*I)/(T*U)
    int B = out_size;

    const int threads = 256;
    const int warpsPerBlock = threads / 32;                 // 8
    const int nwarps = (B + NQ - 1) / NQ;                   // queries per warp
    const int blocks = (nwarps + warpsPerBlock - 1) / warpsPerBlock;

    ucf_kernel<<<blocks, threads>>>(qos, uavg, usim, uid, iid, tidv, topk,
                                    (float*)d_out, U, I, B);
}